// round 2
// baseline (speedup 1.0000x reference)
#include <cuda_runtime.h>

#define N      8192
#define D      256
#define D4     64          // D / 4 (float4)
#define NCLS   10
#define NB     256         // accumulate blocks
#define RPB    32          // rows per block (NB * RPB == N)
#define HRPB   16          // rows per 64-thread subgroup

// Scratch: fully overwritten every launch (graph-replay safe, no zeroing kernel).
__device__ float g_partS[NB][NCLS * D];   // per-block per-class per-dim sums (2.62 MB)
__device__ float g_partQ[NB][NCLS];       // per-block per-class sum of squares
__device__ float g_S[NCLS * D];
__device__ float g_Q[NCLS];

// ---------------------------------------------------------------------------
// Kernel 1: stream the 8 MB input once; per-class sums + sum-of-squares.
// 128 threads/block = two 64-thread subgroups, each with a private shared
// accumulator (halves the serial LDS RMW chain). Within a subgroup, thread
// t owns dims [4t, 4t+4) -> conflict-free.
// ---------------------------------------------------------------------------
__global__ void __launch_bounds__(128) k_accum(const float* __restrict__ x,
                                               const int* __restrict__ lab) {
    __shared__ float4 S4[2][NCLS * D4];   // 20 KB
    __shared__ float4 Q4[2][NCLS * D4];   // 20 KB
    __shared__ int    labs[RPB];
    __shared__ float  qred[4][NCLS];

    const int tid = threadIdx.x;          // 0..127
    const int g   = tid >> 6;             // subgroup 0/1
    const int t   = tid & 63;             // lane-in-subgroup 0..63
    const int b   = blockIdx.x;

    #pragma unroll
    for (int i = t; i < NCLS * D4; i += 64) {
        S4[g][i] = make_float4(0.f, 0.f, 0.f, 0.f);
        Q4[g][i] = make_float4(0.f, 0.f, 0.f, 0.f);
    }
    if (tid < RPB) labs[tid] = lab[b * RPB + tid];
    __syncthreads();

    // Subgroup g handles rows [g*HRPB, (g+1)*HRPB).
    const float4* __restrict__ o4 =
        reinterpret_cast<const float4*>(x) + (size_t)(b * RPB + g * HRPB) * D4 + t;

    #pragma unroll
    for (int r = 0; r < HRPB; r++) {
        float4 v = o4[r * D4];
        int idx = labs[g * HRPB + r] * D4 + t;
        float4 s = S4[g][idx];
        s.x += v.x; s.y += v.y; s.z += v.z; s.w += v.w;
        S4[g][idx] = s;
        float4 q = Q4[g][idx];
        q.x = fmaf(v.x, v.x, q.x); q.y = fmaf(v.y, v.y, q.y);
        q.z = fmaf(v.z, v.z, q.z); q.w = fmaf(v.w, v.w, q.w);
        Q4[g][idx] = q;
    }
    __syncthreads();

    // Merge subgroup 1 into subgroup 0 and dump S partials (no atomics).
    float4* dst = reinterpret_cast<float4*>(g_partS[b]);
    #pragma unroll
    for (int i = tid; i < NCLS * D4; i += 128) {
        float4 a = S4[0][i], c = S4[1][i];
        a.x += c.x; a.y += c.y; a.z += c.z; a.w += c.w;
        dst[i] = a;
    }

    // Reduce Q (both subgroup buffers) to one scalar per class for this block.
    const int lane = tid & 31, w = tid >> 5;     // w in 0..3
    #pragma unroll
    for (int l = 0; l < NCLS; l++) {
        float4 q = Q4[g][l * D4 + t];
        float v = (q.x + q.y) + (q.z + q.w);
        #pragma unroll
        for (int off = 16; off; off >>= 1)
            v += __shfl_down_sync(0xffffffffu, v, off);
        if (lane == 0) qred[w][l] = v;
    }
    __syncthreads();
    if (tid < NCLS)
        g_partQ[b][tid] = (qred[0][tid] + qred[1][tid]) +
                          (qred[2][tid] + qred[3][tid]);
}

// ---------------------------------------------------------------------------
// Kernel 2: reduce the NB block-partials into g_S / g_Q.
// ---------------------------------------------------------------------------
__global__ void k_reduce() {
    const int gid = blockIdx.x * 256 + threadIdx.x;
    if (gid < NCLS * D) {
        float s = 0.f;
        #pragma unroll 8
        for (int b = 0; b < NB; b++) s += g_partS[b][gid];
        g_S[gid] = s;
    } else if (gid < NCLS * D + NCLS) {
        const int l = gid - NCLS * D;
        float s = 0.f;
        #pragma unroll 8
        for (int b = 0; b < NB; b++) s += g_partQ[b][l];
        g_Q[l] = s;
    }
}

// ---------------------------------------------------------------------------
// Kernel 3: epilogue. One block of 256 threads (thread t = dim t).
// ---------------------------------------------------------------------------
__device__ __forceinline__ double block_reduce(double v, double* red, int t) {
    __syncthreads();              // protect prior use of red
    red[t] = v;
    __syncthreads();
    #pragma unroll
    for (int s = 128; s; s >>= 1) {
        if (t < s) red[t] += red[t + s];
        __syncthreads();
    }
    return red[0];
}

__global__ void __launch_bounds__(256) k_final(const float* __restrict__ x,
                                               const int* __restrict__ lab,
                                               float* __restrict__ res) {
    __shared__ double red[256];
    __shared__ int    cnt[NCLS];

    const int t = threadIdx.x;
    if (t < NCLS) cnt[t] = 0;
    __syncthreads();

    // Class counts (register-unrolled: no dynamic indexing, few smem atomics).
    int c[NCLS];
    #pragma unroll
    for (int k = 0; k < NCLS; k++) c[k] = 0;
    for (int i = t; i < N; i += 256) {
        int l = lab[i];
        #pragma unroll
        for (int k = 0; k < NCLS; k++) c[k] += (l == k) ? 1 : 0;
    }
    #pragma unroll
    for (int k = 0; k < NCLS; k++) {
        int v = c[k];
        #pragma unroll
        for (int off = 16; off; off >>= 1)
            v += __shfl_down_sync(0xffffffffu, v, off);
        if ((t & 31) == 0) atomicAdd(&cnt[k], v);   // 80 smem atomics total
    }

    const int firstL = lab[0];
    const int lastL  = lab[N - 1];
    const float v0 = x[t];
    const float vN = x[(size_t)(N - 1) * D + t];

    double dsame = 0.0;
    float satot = 0.f, sbtot = 0.f;
    #pragma unroll
    for (int l = 0; l < NCLS; l++) {
        float s  = g_S[l * D + t];
        float sa = s - ((l == lastL)  ? vN : 0.f);  // rows i in [0, N-1)
        float sb = s - ((l == firstL) ? v0 : 0.f);  // cols j in [1, N)
        dsame += (double)sa * (double)sb;
        satot += sa; sbtot += sb;
    }
    const double dall = (double)satot * (double)sbtot;

    const double dsame_t = block_reduce(dsame, red, t);
    const double dall_t  = block_reduce(dall,  red, t);
    const double sq0_t   = block_reduce((double)v0 * v0, red, t);
    const double sqN_t   = block_reduce((double)vN * vN, red, t);

    if (t == 0) {
        double term12 = 0.0;
        #pragma unroll
        for (int l = 0; l < NCLS; l++) {
            double sqA = (double)g_Q[l] - ((l == lastL)  ? sqN_t : 0.0);
            double sqB = (double)g_Q[l] - ((l == firstL) ? sq0_t : 0.0);
            double cA  = (double)(cnt[l] - ((l == lastL)  ? 1 : 0));
            double cB  = (double)(cnt[l] - ((l == firstL) ? 1 : 0));
            term12 += sqA * (2.0 * cB - (double)(N - 1))
                    + sqB * (2.0 * cA - (double)(N - 1));
        }
        double result = term12 - 2.0 * (2.0 * dsame_t - dall_t);
        const double PAR = 0.5 / (double)N;   // COV * 0.5 / BATCH_SIZE
        res[0] = (float)(PAR * result);
    }
}

extern "C" void kernel_launch(void* const* d_in, const int* in_sizes, int n_in,
                              void* d_out, int out_size) {
    const float* x   = (const float*)d_in[0];
    const int*   lab = (const int*)d_in[1];
    float*       res = (float*)d_out;
    (void)in_sizes; (void)n_in; (void)out_size;

    k_accum<<<NB, 128>>>(x, lab);
    k_reduce<<<(NCLS * D + NCLS + 255) / 256, 256>>>();
    k_final<<<1, 256>>>(x, lab, res);
}

// round 3
// speedup vs baseline: 1.8889x; 1.8889x over previous
#include <cuda_runtime.h>

#define N     8192
#define D     256
#define D4    64           // D/4
#define NCLS  10
#define NB    256          // accumulate blocks
#define RPB   32           // rows per block
#define SG    4            // row-subgroups per block (64 threads each)
#define RPSG  8            // rows per subgroup
#define NSEG  8            // reduce segments
#define BPSEG (NB / NSEG)  // 32 blocks per segment
#define SDIM  (NCLS * D)   // 2560

// Scratch (fully overwritten every launch -> graph-replay safe, no zeroing).
__device__ float g_partS[NB][SDIM];
__device__ float g_partQ[NB][NCLS];
__device__ int   g_partC[NB][NCLS];
__device__ float g_redS[NSEG][SDIM];
__device__ float g_redQ[NSEG][NCLS];
__device__ int   g_redC[NSEG][NCLS];

// ---------------------------------------------------------------------------
// Kernel 1: stream input once. Register-resident per-class accumulators
// (masked FFMA, no shared-memory RMW chain). 256 thr = 4 subgroups x 64;
// thread owns dims [4t,4t+4), subgroup owns 8 rows.
// ---------------------------------------------------------------------------
__global__ void __launch_bounds__(256) k_accum(const float* __restrict__ x,
                                               const int* __restrict__ lab) {
    __shared__ float4 Ssh[NCLS * D4];   // 10 KB merge buffer
    __shared__ int    labs[RPB];
    __shared__ float  qred[8][NCLS];

    const int tid = threadIdx.x;
    const int g   = tid >> 6;           // subgroup 0..3
    const int t   = tid & 63;           // dim-group 0..63
    const int b   = blockIdx.x;

    if (tid < RPB) labs[tid] = lab[b * RPB + tid];
    __syncthreads();

    float4 S[NCLS];
    float  Q[NCLS];
    #pragma unroll
    for (int k = 0; k < NCLS; k++) {
        S[k] = make_float4(0.f, 0.f, 0.f, 0.f);
        Q[k] = 0.f;
    }

    const float4* __restrict__ p =
        reinterpret_cast<const float4*>(x) + (size_t)(b * RPB + g * RPSG) * D4 + t;

    #pragma unroll
    for (int r = 0; r < RPSG; r++) {
        float4 v = p[r * D4];
        int l = labs[g * RPSG + r];
        float q = v.x * v.x;
        q = fmaf(v.y, v.y, q); q = fmaf(v.z, v.z, q); q = fmaf(v.w, v.w, q);
        #pragma unroll
        for (int k = 0; k < NCLS; k++) {
            float m = (l == k) ? 1.f : 0.f;
            S[k].x = fmaf(m, v.x, S[k].x);
            S[k].y = fmaf(m, v.y, S[k].y);
            S[k].z = fmaf(m, v.z, S[k].z);
            S[k].w = fmaf(m, v.w, S[k].w);
            Q[k]   = fmaf(m, q,   Q[k]);
        }
    }

    // Merge the 4 subgroups' register S into shared (serialized, conflict-free).
    #pragma unroll
    for (int gi = 0; gi < SG; gi++) {
        if (g == gi) {
            if (gi == 0) {
                #pragma unroll
                for (int k = 0; k < NCLS; k++) Ssh[k * D4 + t] = S[k];
            } else {
                #pragma unroll
                for (int k = 0; k < NCLS; k++) {
                    float4 a = Ssh[k * D4 + t];
                    a.x += S[k].x; a.y += S[k].y; a.z += S[k].z; a.w += S[k].w;
                    Ssh[k * D4 + t] = a;
                }
            }
        }
        __syncthreads();
    }

    // Dump S partials (10 KB / block, no atomics).
    float4* dst = reinterpret_cast<float4*>(g_partS[b]);
    #pragma unroll
    for (int i = tid; i < NCLS * D4; i += 256) dst[i] = Ssh[i];

    // Reduce per-thread Q[k] across block via shfl + small smem pass.
    const int lane = tid & 31, w = tid >> 5;
    #pragma unroll
    for (int k = 0; k < NCLS; k++) {
        float v = Q[k];
        #pragma unroll
        for (int off = 16; off; off >>= 1)
            v += __shfl_down_sync(0xffffffffu, v, off);
        if (lane == 0) qred[w][k] = v;
    }
    __syncthreads();
    if (tid < NCLS) {
        float s = 0.f;
        #pragma unroll
        for (int w2 = 0; w2 < 8; w2++) s += qred[w2][tid];
        g_partQ[b][tid] = s;
    }

    // Per-block class counts from the 32 cached labels (one warp).
    if (tid < 32) {
        int l = labs[tid];
        #pragma unroll
        for (int k = 0; k < NCLS; k++) {
            unsigned m = __ballot_sync(0xffffffffu, l == k);
            if (tid == 0) g_partC[b][k] = __popc(m);
        }
    }
}

// ---------------------------------------------------------------------------
// Kernel 2: 2-D reduce. Block (x,y): x covers outputs, y = segment of 32
// blocks. Each thread sums 32 partials (fully unrolled -> high MLP).
// ---------------------------------------------------------------------------
__global__ void __launch_bounds__(128) k_reduce() {
    const int gid = blockIdx.x * 128 + threadIdx.x;
    const int s   = blockIdx.y;
    const int b0  = s * BPSEG;
    if (gid < SDIM) {
        float acc = 0.f;
        #pragma unroll
        for (int i = 0; i < BPSEG; i++) acc += g_partS[b0 + i][gid];
        g_redS[s][gid] = acc;
    } else if (gid < SDIM + NCLS) {
        const int l = gid - SDIM;
        float acc = 0.f;
        #pragma unroll
        for (int i = 0; i < BPSEG; i++) acc += g_partQ[b0 + i][l];
        g_redQ[s][l] = acc;
    } else if (gid < SDIM + 2 * NCLS) {
        const int l = gid - SDIM - NCLS;
        int acc = 0;
        #pragma unroll
        for (int i = 0; i < BPSEG; i++) acc += g_partC[b0 + i][l];
        g_redC[s][l] = acc;
    }
}

// ---------------------------------------------------------------------------
// Kernel 3: epilogue, one block of 256 threads (thread t = dim t).
// ---------------------------------------------------------------------------
__device__ __forceinline__ double block_reduce(double v, double* red, int t) {
    __syncthreads();
    red[t] = v;
    __syncthreads();
    #pragma unroll
    for (int s = 128; s; s >>= 1) {
        if (t < s) red[t] += red[t + s];
        __syncthreads();
    }
    return red[0];
}

__global__ void __launch_bounds__(256) k_final(const float* __restrict__ x,
                                               const int* __restrict__ lab,
                                               float* __restrict__ res) {
    __shared__ double red[256];
    __shared__ float  Qs[NCLS];
    __shared__ int    Cs[NCLS];

    const int t = threadIdx.x;
    if (t < NCLS) {
        float q = 0.f; int c = 0;
        #pragma unroll
        for (int s = 0; s < NSEG; s++) { q += g_redQ[s][t]; c += g_redC[s][t]; }
        Qs[t] = q; Cs[t] = c;
    }
    const int firstL = lab[0];
    const int lastL  = lab[N - 1];
    const float v0 = x[t];
    const float vN = x[(size_t)(N - 1) * D + t];
    __syncthreads();

    double dsame = 0.0;
    float satot = 0.f, sbtot = 0.f;
    #pragma unroll
    for (int l = 0; l < NCLS; l++) {
        float s = 0.f;
        #pragma unroll
        for (int sg = 0; sg < NSEG; sg++) s += g_redS[sg][l * D + t];
        float sa = s - ((l == lastL)  ? vN : 0.f);   // rows i in [0, N-1)
        float sb = s - ((l == firstL) ? v0 : 0.f);   // cols j in [1, N)
        dsame += (double)sa * (double)sb;
        satot += sa; sbtot += sb;
    }
    const double dall = (double)satot * (double)sbtot;

    const double dsame_t = block_reduce(dsame, red, t);
    const double dall_t  = block_reduce(dall,  red, t);
    const double sq0_t   = block_reduce((double)v0 * v0, red, t);
    const double sqN_t   = block_reduce((double)vN * vN, red, t);

    if (t == 0) {
        double term12 = 0.0;
        #pragma unroll
        for (int l = 0; l < NCLS; l++) {
            double sqA = (double)Qs[l] - ((l == lastL)  ? sqN_t : 0.0);
            double sqB = (double)Qs[l] - ((l == firstL) ? sq0_t : 0.0);
            double cA  = (double)(Cs[l] - ((l == lastL)  ? 1 : 0));
            double cB  = (double)(Cs[l] - ((l == firstL) ? 1 : 0));
            term12 += sqA * (2.0 * cB - (double)(N - 1))
                    + sqB * (2.0 * cA - (double)(N - 1));
        }
        double result = term12 - 2.0 * (2.0 * dsame_t - dall_t);
        const double PAR = 0.5 / (double)N;   // COV * 0.5 / BATCH_SIZE
        res[0] = (float)(PAR * result);
    }
}

extern "C" void kernel_launch(void* const* d_in, const int* in_sizes, int n_in,
                              void* d_out, int out_size) {
    const float* x   = (const float*)d_in[0];
    const int*   lab = (const int*)d_in[1];
    float*       res = (float*)d_out;
    (void)in_sizes; (void)n_in; (void)out_size;

    k_accum<<<NB, 256>>>(x, lab);
    dim3 rg((SDIM + 2 * NCLS + 127) / 128, NSEG);
    k_reduce<<<rg, 128>>>();
    k_final<<<1, 256>>>(x, lab, res);
}